// round 14
// baseline (speedup 1.0000x reference)
#include <cuda_runtime.h>
#include <cuda_fp16.h>
#include <cstdint>
#include <cstring>

typedef unsigned long long u64;
typedef unsigned int u32;

#define BATCH 4
#define LDIM 4800
#define SDIM 4800
#define CDIM 256
#define KPK 256
#define EXP_SCALE (1.442695041f/25.6f)  // log2(e)/(C*TEMP)

// output layout (float32, concatenated reference outputs)
#define OFF_MATCH 92160000u
#define OFF_SID   92179200u
#define OFF_MCONF 92198400u
#define OFF_MK0   92217600u
#define OFF_MK1   92227200u
#define TOTAL_OUT 92265600u

// ---------------- device scratch ----------------
__device__ __half g_sim[(size_t)BATCH * LDIM * SDIM];  // exp(sim) in fp16
__device__ __half g_a[(size_t)BATCH * LDIM * KPK];
__device__ __half g_b[(size_t)BATCH * SDIM * KPK];
__device__ float g_rowZ[BATCH * LDIM];
__device__ float g_colZ[BATCH * SDIM];
__device__ u32   g_colMax[BATCH * SDIM];
__device__ u32   g_mask[(size_t)BATCH * LDIM * 152];   // 150 words + pad per row

// ---------------- helpers ----------------
__device__ __forceinline__ u32 h2_bits(__half2 h) {
    u32 r; memcpy(&r, &h, 4); return r;
}
__device__ __forceinline__ u32 smem_u32(const void* p) {
    u32 a;
    asm("{ .reg .u64 t; cvta.to.shared.u64 t, %1; cvt.u32.u64 %0, t; }"
        : "=r"(a) : "l"(p));
    return a;
}
__device__ __forceinline__ void cpasync16(u32 dst, const void* src) {
    asm volatile("cp.async.cg.shared.global [%0], [%1], 16;"
                 :: "r"(dst), "l"(src) : "memory");
}
#define CP_COMMIT() asm volatile("cp.async.commit_group;" ::: "memory")
#define CP_WAIT(n)  asm volatile("cp.async.wait_group %0;" :: "n"(n) : "memory")

__device__ __forceinline__ void ldsm4(u32& r0, u32& r1, u32& r2, u32& r3, u32 addr) {
    asm volatile("ldmatrix.sync.aligned.m8n8.x4.shared.b16 {%0,%1,%2,%3}, [%4];"
                 : "=r"(r0), "=r"(r1), "=r"(r2), "=r"(r3) : "r"(addr));
}
__device__ __forceinline__ void mma16816(float* d, const u32* a, const u32* b) {
    asm volatile(
        "mma.sync.aligned.m16n8k16.row.col.f32.f16.f16.f32 "
        "{%0,%1,%2,%3}, {%4,%5,%6,%7}, {%8,%9}, {%0,%1,%2,%3};"
        : "+f"(d[0]), "+f"(d[1]), "+f"(d[2]), "+f"(d[3])
        : "r"(a[0]), "r"(a[1]), "r"(a[2]), "r"(a[3]), "r"(b[0]), "r"(b[1]));
}
__device__ __forceinline__ float ex2f(float x) {
    float r; asm("ex2.approx.f32 %0, %1;" : "=f"(r) : "f"(x)); return r;
}

// ---------------- K_prep: fp32 -> fp16 ; fused init ----------------
__global__ void prep_kernel(const float* __restrict__ f0,
                            const float* __restrict__ f1,
                            float* __restrict__ out, int full)
{
    int idx = blockIdx.x * blockDim.x + threadIdx.x;

    if (idx < BATCH * SDIM) { g_colZ[idx] = 0.f; g_colMax[idx] = 0u; }
    if (idx < BATCH * LDIM) g_rowZ[idx] = 0.f;
    if (full && idx < LDIM) {
        out[OFF_MK0 + 2 * idx]     = (float)(idx % 80) * 8.f;
        out[OFF_MK0 + 2 * idx + 1] = (float)(idx / 80) * 8.f;
    }

    const int TOT = (BATCH * LDIM * CDIM) / 4;
    if (idx >= TOT) return;
    float4 x0 = *(const float4*)(f0 + idx * 4);
    float4 x1 = *(const float4*)(f1 + idx * 4);
    u32 a01 = h2_bits(__floats2half2_rn(x0.x, x0.y));
    u32 a23 = h2_bits(__floats2half2_rn(x0.z, x0.w));
    u32 b01 = h2_bits(__floats2half2_rn(x1.x, x1.y));
    u32 b23 = h2_bits(__floats2half2_rn(x1.z, x1.w));
    *(uint2*)(g_a + idx * 4) = make_uint2(a01, a23);
    *(uint2*)(g_b + idx * 4) = make_uint2(b01, b23);
}

// ---------------- K_gemm: 3-stage BK=16 pipeline + fused exp/sums + staged store ----
#define PADB 48      // 32B payload + 16B pad: conflict-free at stride 48
#define NCH  16      // K=256 in 16 chunks of 16
#define STAGES 3
#define STGW 136     // staging row stride in halves (272B)
#define ABUF (128 * PADB)   // 6144 B per stage per matrix

__global__ void __launch_bounds__(256, 2) gemm_kernel()
{
    // 6 stage buffers (36864 B), reused as 128x136-half e-staging (34816 B)
    __shared__ __align__(16) char sm[2 * STAGES * ABUF];

    const int tid  = threadIdx.x;
    const int wid  = tid >> 5;
    const int lane = tid & 31;
    const int b    = blockIdx.z;
    const int l0   = blockIdx.y * 128;
    const int s0   = blockIdx.x * 128;
    const int wm   = wid & 1;
    const int wn   = wid >> 1;

    const __half* gA = g_a + (size_t)b * LDIM * KPK;
    const __half* gB = g_b + (size_t)b * SDIM * KPK;
    u32 base = smem_u32(sm);
    u32 aA[STAGES], aB[STAGES];
    #pragma unroll
    for (int s = 0; s < STAGES; s++) {
        aA[s] = base + s * ABUF;
        aB[s] = base + (STAGES + s) * ABUF;
    }

    const int lrow0 = tid >> 1;         // 0..127
    const int lpart = tid & 1;          // 0..1 (16B halves of 32B row)

    float acc[4][4][4];
    #pragma unroll
    for (int i = 0; i < 4; i++)
        #pragma unroll
        for (int j = 0; j < 4; j++)
            #pragma unroll
            for (int v = 0; v < 4; v++) acc[i][j][v] = 0.f;

    auto load_chunk = [&](int ch, int buf) {
        u32 off = (u32)(lrow0 * PADB + lpart * 16);
        int gl = l0 + lrow0; if (gl > LDIM - 1) gl = LDIM - 1;
        cpasync16(aA[buf] + off, gA + (size_t)gl * KPK + ch * 16 + lpart * 8);
        int gs = s0 + lrow0; if (gs > SDIM - 1) gs = SDIM - 1;
        cpasync16(aB[buf] + off, gB + (size_t)gs * KPK + ch * 16 + lpart * 8);
        CP_COMMIT();
    };

    load_chunk(0, 0);
    load_chunk(1, 1);

    const int rsel = (lane & 7) + ((lane >> 3) & 1) * 8;
    const int ksel = lane >> 4;

    #pragma unroll 1
    for (int ch = 0; ch < NCH; ch++) {
        if (ch < NCH - 2)      { load_chunk(ch + 2, (ch + 2) % STAGES); CP_WAIT(2); }
        else if (ch == NCH - 2) CP_WAIT(1);
        else                    CP_WAIT(0);
        __syncthreads();
        u32 bufA = aA[ch % STAGES], bufB = aB[ch % STAGES];

        u32 a[4][4], bb[4][2];
        #pragma unroll
        for (int mf = 0; mf < 4; mf++) {
            int row = wm * 64 + mf * 16 + rsel;
            ldsm4(a[mf][0], a[mf][1], a[mf][2], a[mf][3],
                  bufA + (u32)(row * PADB + ksel * 16));
        }
        #pragma unroll
        for (int np = 0; np < 2; np++) {
            int row = wn * 32 + np * 16 + rsel;
            u32 r0, r1, r2, r3;
            ldsm4(r0, r1, r2, r3,
                  bufB + (u32)(row * PADB + ksel * 16));
            bb[np * 2][0]     = r0; bb[np * 2][1]     = r2;
            bb[np * 2 + 1][0] = r1; bb[np * 2 + 1][1] = r3;
        }
        #pragma unroll
        for (int mf = 0; mf < 4; mf++)
            #pragma unroll
            for (int nf = 0; nf < 4; nf++)
                mma16816(acc[mf][nf], a[mf], bb[nf]);
        __syncthreads();
    }

    // ---- fused epilogue: e = exp(dot/25.6) fp32, stage fp16 in smem, sums ----
    const int mrow0 = l0 + wm * 64;
    const int ncol0 = s0 + wn * 32;
    const int r_in  = lane >> 2;
    const int c_in  = (lane & 3) * 2;
    __half* stg = (__half*)sm;   // 128 x STGW halves

    float rsum[4][2];
    float csum[4][2];
    #pragma unroll
    for (int i = 0; i < 4; i++) { rsum[i][0] = rsum[i][1] = 0.f; csum[i][0] = csum[i][1] = 0.f; }

    #pragma unroll
    for (int mf = 0; mf < 4; mf++) {
        #pragma unroll
        for (int half = 0; half < 2; half++) {
            int lrow = wm * 64 + mf * 16 + half * 8 + r_in;   // local 0..127
            int row  = l0 + lrow;
            bool rok = row < LDIM;
            #pragma unroll
            for (int nf = 0; nf < 4; nf++) {
                int col = ncol0 + nf * 8 + c_in;
                bool ok = rok && (col < SDIM);
                float e0 = ok ? ex2f(acc[mf][nf][half * 2]     * EXP_SCALE) : 0.f;
                float e1 = ok ? ex2f(acc[mf][nf][half * 2 + 1] * EXP_SCALE) : 0.f;
                *(__half2*)(stg + lrow * STGW + wn * 32 + nf * 8 + c_in) =
                    __floats2half2_rn(e0, e1);
                rsum[mf][half] += e0 + e1;
                csum[nf][0] += e0;
                csum[nf][1] += e1;
            }
        }
    }
    #pragma unroll
    for (int mf = 0; mf < 4; mf++)
        #pragma unroll
        for (int half = 0; half < 2; half++) {
            float v = rsum[mf][half];
            v += __shfl_xor_sync(0xffffffffu, v, 1);
            v += __shfl_xor_sync(0xffffffffu, v, 2);
            if ((lane & 3) == 0) {
                int row = mrow0 + mf * 16 + half * 8 + r_in;
                if (row < LDIM) atomicAdd(&g_rowZ[b * LDIM + row], v);
            }
        }
    #pragma unroll
    for (int nf = 0; nf < 4; nf++)
        #pragma unroll
        for (int p = 0; p < 2; p++) {
            float v = csum[nf][p];
            v += __shfl_xor_sync(0xffffffffu, v, 4);
            v += __shfl_xor_sync(0xffffffffu, v, 8);
            v += __shfl_xor_sync(0xffffffffu, v, 16);
            if (lane < 4) {
                int col = ncol0 + nf * 8 + (lane & 3) * 2 + p;
                if (col < SDIM) atomicAdd(&g_colZ[b * SDIM + col], v);
            }
        }

    __syncthreads();
    // ---- coalesced copy-out: 16 rows x 16 chunks (uint4 = 8 halves) per iter ----
    {
        const int crow = tid >> 4;          // 0..15
        const int cchk = tid & 15;          // 0..15
        #pragma unroll
        for (int it = 0; it < 8; it++) {
            int lrow = it * 16 + crow;
            int grow = l0 + lrow;
            int gcol = s0 + cchk * 8;
            uint4 v = *(const uint4*)(stg + lrow * STGW + cchk * 8);
            if (grow < LDIM && gcol + 7 < SDIM)
                __stcs((uint4*)(g_sim + ((size_t)b * LDIM + grow) * SDIM + gcol), v);
        }
    }
}

// ---------------- K_conf: conf = e^2/(rowZ*colZ), colMax, candidate bitmask ----------------
#define CSLOT 3
#define RPB 8
#define CTHREADS 512
__global__ void __launch_bounds__(CTHREADS, 2) conf_kernel(float* __restrict__ out)
{
    const int b    = blockIdx.y;
    const int lc   = blockIdx.x;
    const int tid  = threadIdx.x;
    const int lane = tid & 31;
    const int bi0  = b * LDIM + lc * RPB;

    float4 colInv[CSLOT], cmax[CSLOT];
    u32 bnib = 0;
    #pragma unroll
    for (int j = 0; j < CSLOT; j++) {
        int s4 = tid + j * CTHREADS;
        if (s4 < 1200) {
            colInv[j] = *(const float4*)(g_colZ + b * SDIM + s4 * 4);
            colInv[j].x = 1.f / colInv[j].x;
            colInv[j].y = 1.f / colInv[j].y;
            colInv[j].z = 1.f / colInv[j].z;
            colInv[j].w = 1.f / colInv[j].w;
            u32 nib = 0;
            #pragma unroll
            for (int k = 0; k < 4; k++) {
                int s = s4 * 4 + k;
                int sh = s / 80, sw = s % 80;
                if (sh >= 2 && sh < 58 && sw >= 2 && sw < 78) nib |= (1u << k);
            }
            bnib |= nib << (4 * j);
        } else {
            colInv[j] = make_float4(0.f, 0.f, 0.f, 0.f);
        }
        cmax[j] = make_float4(0.f, 0.f, 0.f, 0.f);
    }

    float4 rz0 = *(const float4*)(g_rowZ + bi0);
    float4 rz1 = *(const float4*)(g_rowZ + bi0 + 4);
    float rowInvA[RPB] = { 1.f/rz0.x, 1.f/rz0.y, 1.f/rz0.z, 1.f/rz0.w,
                           1.f/rz1.x, 1.f/rz1.y, 1.f/rz1.z, 1.f/rz1.w };

    uint2 ecur[CSLOT], enext[CSLOT];
    {
        const uint2* er = (const uint2*)(g_sim + (size_t)bi0 * SDIM);
        #pragma unroll
        for (int j = 0; j < CSLOT; j++) {
            int s4 = tid + j * CTHREADS;
            ecur[j] = (s4 < 1200) ? __ldcs(er + s4) : make_uint2(0u, 0u);
        }
    }

    for (int r = 0; r < RPB; r++) {
        if (r < RPB - 1) {
            const uint2* er = (const uint2*)(g_sim + (size_t)(bi0 + r + 1) * SDIM);
            #pragma unroll
            for (int j = 0; j < CSLOT; j++) {
                int s4 = tid + j * CTHREADS;
                enext[j] = (s4 < 1200) ? __ldcs(er + s4) : make_uint2(0u, 0u);
            }
        }
        int l  = lc * RPB + r;
        int bi = bi0 + r;
        float rowInv = rowInvA[r];
        int lh = l / 80, lw = l % 80;
        bool lval = (lh >= 2) && (lh < 58) && (lw >= 2) && (lw < 78);
        float4* orow = (float4*)(out + (size_t)bi * SDIM);
        u32* mrow = g_mask + (size_t)bi * 152;
        #pragma unroll
        for (int j = 0; j < CSLOT; j++) {
            int s4 = tid + j * CTHREADS;
            u32 nib = 0;
            if (s4 < 1200) {
                __half2 h01, h23;
                memcpy(&h01, &ecur[j].x, 4);
                memcpy(&h23, &ecur[j].y, 4);
                float2 e01 = __half22float2(h01);
                float2 e23 = __half22float2(h23);
                float4 c;
                c.x = e01.x * e01.x * rowInv * colInv[j].x;
                c.y = e01.y * e01.y * rowInv * colInv[j].y;
                c.z = e23.x * e23.x * rowInv * colInv[j].z;
                c.w = e23.y * e23.y * rowInv * colInv[j].w;
                __stcs(orow + s4, c);
                cmax[j].x = fmaxf(cmax[j].x, c.x);
                cmax[j].y = fmaxf(cmax[j].y, c.y);
                cmax[j].z = fmaxf(cmax[j].z, c.z);
                cmax[j].w = fmaxf(cmax[j].w, c.w);
                if (lval) {
                    if (c.x > 0.2f) nib |= 1u;
                    if (c.y > 0.2f) nib |= 2u;
                    if (c.z > 0.2f) nib |= 4u;
                    if (c.w > 0.2f) nib |= 8u;
                    nib &= (bnib >> (4 * j)) & 15u;
                }
            }
            u32 v = nib << ((lane & 7) * 4);
            v |= __shfl_xor_sync(0xffffffffu, v, 1);
            v |= __shfl_xor_sync(0xffffffffu, v, 2);
            v |= __shfl_xor_sync(0xffffffffu, v, 4);
            if ((lane & 7) == 0) {
                int w = (tid + j * CTHREADS) >> 3;
                if (w < 150 && (tid + j * CTHREADS) < 1200) mrow[w] = v;
            }
        }
        #pragma unroll
        for (int j = 0; j < CSLOT; j++) ecur[j] = enext[j];
    }
    #pragma unroll
    for (int j = 0; j < CSLOT; j++) {
        int s4 = tid + j * CTHREADS;
        if (s4 < 1200) {
            u32* cm = g_colMax + b * SDIM + s4 * 4;
            atomicMax(cm + 0, __float_as_uint(cmax[j].x));
            atomicMax(cm + 1, __float_as_uint(cmax[j].y));
            atomicMax(cm + 2, __float_as_uint(cmax[j].z));
            atomicMax(cm + 3, __float_as_uint(cmax[j].w));
        }
    }
}

// ---------------- K_match: one warp per row, scans candidate bitmask ----------------
__global__ void __launch_bounds__(256) match_kernel(float* __restrict__ out)
{
    const int wid  = threadIdx.x >> 5;
    const int lane = threadIdx.x & 31;
    const int bi   = blockIdx.x * 8 + wid;
    const int b    = bi / LDIM;

    const u32* mrow = g_mask + (size_t)bi * 152;
    u64 best = 0ull;
    for (int w = lane; w < 150; w += 32) {
        u32 m = mrow[w];
        while (m) {
            int bit = __ffs(m) - 1;
            m &= m - 1;
            int s = (w << 5) + bit;
            u64 key = ((u64)g_colMax[b * SDIM + s] << 32)
                    | (u64)(0xFFFFFFFFu - (u32)s);
            if (key > best) best = key;
        }
    }
    #pragma unroll
    for (int o = 16; o; o >>= 1) {
        u64 v = __shfl_xor_sync(0xffffffffu, best, o);
        if (v > best) best = v;
    }
    if (lane == 0) {
        float match = 0.f, sid = 0.f, mc = 0.f, kx = 0.f, ky = 0.f;
        if (best) {
            int s = (int)(0xFFFFFFFFu - (u32)(best & 0xFFFFFFFFull));
            match = 1.f;
            sid = (float)s;
            mc = out[(size_t)bi * SDIM + s];
            kx = (float)(s % 80) * 8.f;
            ky = (float)(s / 80) * 8.f;
        }
        out[OFF_MATCH + bi] = match;
        out[OFF_SID   + bi] = sid;
        out[OFF_MCONF + bi] = mc;
        out[OFF_MK1 + (size_t)bi * 2]     = kx;
        out[OFF_MK1 + (size_t)bi * 2 + 1] = ky;
    }
}

extern "C" void kernel_launch(void* const* d_in, const int* in_sizes, int n_in,
                              void* d_out, int out_size)
{
    const float* f0 = (const float*)d_in[0];
    const float* f1 = (const float*)d_in[1];
    float* out = (float*)d_out;
    const bool full = ((unsigned)out_size >= TOTAL_OUT);

    const int TOT = (BATCH * LDIM * CDIM) / 4;
    prep_kernel<<<(TOT + 255) / 256, 256>>>(f0, f1, out, full ? 1 : 0);

    dim3 gg((SDIM + 127) / 128, (LDIM + 127) / 128, BATCH);
    gemm_kernel<<<gg, 256>>>();

    dim3 gc(LDIM / RPB, BATCH);
    conf_kernel<<<gc, CTHREADS>>>(out);

    if (full) match_kernel<<<(BATCH * LDIM) / 8, 256>>>(out);
}

// round 15
// speedup vs baseline: 1.1387x; 1.1387x over previous
#include <cuda_runtime.h>
#include <cuda_fp16.h>
#include <cstdint>
#include <cstring>

typedef unsigned long long u64;
typedef unsigned int u32;

#define BATCH 4
#define LDIM 4800
#define SDIM 4800
#define CDIM 256
#define KPK 256
#define EXP_SCALE (1.442695041f/25.6f)  // log2(e)/(C*TEMP)

// output layout (float32, concatenated reference outputs)
#define OFF_MATCH 92160000u
#define OFF_SID   92179200u
#define OFF_MCONF 92198400u
#define OFF_MK0   92217600u
#define OFF_MK1   92227200u
#define TOTAL_OUT 92265600u

// ---------------- device scratch ----------------
__device__ __half g_sim[(size_t)BATCH * LDIM * SDIM];  // exp(sim) in fp16
__device__ __half g_a[(size_t)BATCH * LDIM * KPK];
__device__ __half g_b[(size_t)BATCH * SDIM * KPK];
__device__ float g_rowZ[BATCH * LDIM];
__device__ float g_colZ[BATCH * SDIM];
__device__ u32   g_colMax[BATCH * SDIM];
__device__ u32   g_mask[(size_t)BATCH * LDIM * 152];   // 150 words + pad per row

// ---------------- helpers ----------------
__device__ __forceinline__ u32 h2_bits(__half2 h) {
    u32 r; memcpy(&r, &h, 4); return r;
}
__device__ __forceinline__ u32 smem_u32(const void* p) {
    u32 a;
    asm("{ .reg .u64 t; cvta.to.shared.u64 t, %1; cvt.u32.u64 %0, t; }"
        : "=r"(a) : "l"(p));
    return a;
}
__device__ __forceinline__ void cpasync16(u32 dst, const void* src) {
    asm volatile("cp.async.cg.shared.global [%0], [%1], 16;"
                 :: "r"(dst), "l"(src) : "memory");
}
#define CP_COMMIT() asm volatile("cp.async.commit_group;" ::: "memory")
#define CP_WAIT(n)  asm volatile("cp.async.wait_group %0;" :: "n"(n) : "memory")

__device__ __forceinline__ void ldsm4(u32& r0, u32& r1, u32& r2, u32& r3, u32 addr) {
    asm volatile("ldmatrix.sync.aligned.m8n8.x4.shared.b16 {%0,%1,%2,%3}, [%4];"
                 : "=r"(r0), "=r"(r1), "=r"(r2), "=r"(r3) : "r"(addr));
}
__device__ __forceinline__ void mma16816(float* d, const u32* a, const u32* b) {
    asm volatile(
        "mma.sync.aligned.m16n8k16.row.col.f32.f16.f16.f32 "
        "{%0,%1,%2,%3}, {%4,%5,%6,%7}, {%8,%9}, {%0,%1,%2,%3};"
        : "+f"(d[0]), "+f"(d[1]), "+f"(d[2]), "+f"(d[3])
        : "r"(a[0]), "r"(a[1]), "r"(a[2]), "r"(a[3]), "r"(b[0]), "r"(b[1]));
}
__device__ __forceinline__ float ex2f(float x) {
    float r; asm("ex2.approx.f32 %0, %1;" : "=f"(r) : "f"(x)); return r;
}

// ---------------- K_prep: fp32 -> fp16 ; fused init ----------------
__global__ void prep_kernel(const float* __restrict__ f0,
                            const float* __restrict__ f1,
                            float* __restrict__ out, int full)
{
    int idx = blockIdx.x * blockDim.x + threadIdx.x;

    if (idx < BATCH * SDIM) { g_colZ[idx] = 0.f; g_colMax[idx] = 0u; }
    if (idx < BATCH * LDIM) g_rowZ[idx] = 0.f;
    if (full && idx < LDIM) {
        out[OFF_MK0 + 2 * idx]     = (float)(idx % 80) * 8.f;
        out[OFF_MK0 + 2 * idx + 1] = (float)(idx / 80) * 8.f;
    }

    const int TOT = (BATCH * LDIM * CDIM) / 4;
    if (idx >= TOT) return;
    float4 x0 = *(const float4*)(f0 + idx * 4);
    float4 x1 = *(const float4*)(f1 + idx * 4);
    u32 a01 = h2_bits(__floats2half2_rn(x0.x, x0.y));
    u32 a23 = h2_bits(__floats2half2_rn(x0.z, x0.w));
    u32 b01 = h2_bits(__floats2half2_rn(x1.x, x1.y));
    u32 b23 = h2_bits(__floats2half2_rn(x1.z, x1.w));
    *(uint2*)(g_a + idx * 4) = make_uint2(a01, a23);
    *(uint2*)(g_b + idx * 4) = make_uint2(b01, b23);
}

// ---------------- K_gemm: 2-stage BK=32 + fused exp/sums + staged coalesced store ----
#define PADB 80
#define NCH  8
#define STGW 136   // staging row stride in halves (272B, conflict-free)

__global__ void __launch_bounds__(256, 2) gemm_kernel()
{
    // 40960 B: mainloop double buffers; reused as 128x136-half e-staging (34816 B)
    __shared__ __align__(16) char sm[2 * 128 * PADB * 2];

    const int tid  = threadIdx.x;
    const int wid  = tid >> 5;
    const int lane = tid & 31;
    const int b    = blockIdx.z;
    const int l0   = blockIdx.y * 128;
    const int s0   = blockIdx.x * 128;
    const int wm   = wid & 1;
    const int wn   = wid >> 1;

    const __half* gA = g_a + (size_t)b * LDIM * KPK;
    const __half* gB = g_b + (size_t)b * SDIM * KPK;
    u32 base = smem_u32(sm);
    u32 aA[2] = { base,               base + 128 * PADB };
    u32 aB[2] = { base + 2*128*PADB,  base + 3*128*PADB };

    const int lrow0 = tid >> 2;
    const int lpart = tid & 3;

    float acc[4][4][4];
    #pragma unroll
    for (int i = 0; i < 4; i++)
        #pragma unroll
        for (int j = 0; j < 4; j++)
            #pragma unroll
            for (int v = 0; v < 4; v++) acc[i][j][v] = 0.f;

    auto load_chunk = [&](int ch, int buf) {
        #pragma unroll
        for (int i = 0; i < 2; i++) {
            int row = lrow0 + i * 64;
            u32 off = (u32)(row * PADB + lpart * 16);
            int gl = l0 + row; if (gl > LDIM - 1) gl = LDIM - 1;
            cpasync16(aA[buf] + off, gA + (size_t)gl * KPK + ch * 32 + lpart * 8);
            int gs = s0 + row; if (gs > SDIM - 1) gs = SDIM - 1;
            cpasync16(aB[buf] + off, gB + (size_t)gs * KPK + ch * 32 + lpart * 8);
        }
        CP_COMMIT();
    };

    load_chunk(0, 0);

    const int rsel = (lane & 7) + ((lane >> 3) & 1) * 8;
    const int ksel = lane >> 4;

    #pragma unroll 1
    for (int ch = 0; ch < NCH; ch++) {
        if (ch < NCH - 1) { load_chunk(ch + 1, (ch + 1) & 1); CP_WAIT(1); }
        else              { CP_WAIT(0); }
        __syncthreads();
        u32 bufA = aA[ch & 1], bufB = aB[ch & 1];

        #pragma unroll
        for (int kk = 0; kk < 2; kk++) {
            u32 a[4][4], bb[4][2];
            #pragma unroll
            for (int mf = 0; mf < 4; mf++) {
                int row = wm * 64 + mf * 16 + rsel;
                ldsm4(a[mf][0], a[mf][1], a[mf][2], a[mf][3],
                      bufA + (u32)(row * PADB + kk * 32 + ksel * 16));
            }
            #pragma unroll
            for (int np = 0; np < 2; np++) {
                int row = wn * 32 + np * 16 + rsel;
                u32 r0, r1, r2, r3;
                ldsm4(r0, r1, r2, r3,
                      bufB + (u32)(row * PADB + kk * 32 + ksel * 16));
                bb[np * 2][0]     = r0; bb[np * 2][1]     = r2;
                bb[np * 2 + 1][0] = r1; bb[np * 2 + 1][1] = r3;
            }
            #pragma unroll
            for (int mf = 0; mf < 4; mf++)
                #pragma unroll
                for (int nf = 0; nf < 4; nf++)
                    mma16816(acc[mf][nf], a[mf], bb[nf]);
        }
        __syncthreads();
    }

    // ---- fused epilogue: e = exp fp32, stage fp16 in smem; sums AFTER store issue ----
    const int mrow0 = l0 + wm * 64;
    const int ncol0 = s0 + wn * 32;
    const int r_in  = lane >> 2;
    const int c_in  = (lane & 3) * 2;
    __half* stg = (__half*)sm;   // 128 x STGW halves

    float rsum[4][2];
    float csum[4][2];
    #pragma unroll
    for (int i = 0; i < 4; i++) { rsum[i][0] = rsum[i][1] = 0.f; csum[i][0] = csum[i][1] = 0.f; }

    #pragma unroll
    for (int mf = 0; mf < 4; mf++) {
        #pragma unroll
        for (int half = 0; half < 2; half++) {
            int lrow = wm * 64 + mf * 16 + half * 8 + r_in;   // local 0..127
            int row  = l0 + lrow;
            bool rok = row < LDIM;
            #pragma unroll
            for (int nf = 0; nf < 4; nf++) {
                int col = ncol0 + nf * 8 + c_in;
                bool ok = rok && (col < SDIM);
                float e0 = ok ? ex2f(acc[mf][nf][half * 2]     * EXP_SCALE) : 0.f;
                float e1 = ok ? ex2f(acc[mf][nf][half * 2 + 1] * EXP_SCALE) : 0.f;
                *(__half2*)(stg + lrow * STGW + wn * 32 + nf * 8 + c_in) =
                    __floats2half2_rn(e0, e1);
                rsum[mf][half] += e0 + e1;
                csum[nf][0] += e0;
                csum[nf][1] += e1;
            }
        }
    }
    __syncthreads();
    // copy-out stores FIRST (fire-and-forget), reductions overlap the drain
    {
        const int crow = tid >> 4;          // 0..15
        const int cchk = tid & 15;          // 0..15
        #pragma unroll
        for (int it = 0; it < 8; it++) {
            int lrow = it * 16 + crow;
            int grow = l0 + lrow;
            int gcol = s0 + cchk * 8;
            uint4 v = *(const uint4*)(stg + lrow * STGW + cchk * 8);
            if (grow < LDIM && gcol + 7 < SDIM)
                __stcs((uint4*)(g_sim + ((size_t)b * LDIM + grow) * SDIM + gcol), v);
        }
    }
    // reductions after store issue
    #pragma unroll
    for (int mf = 0; mf < 4; mf++)
        #pragma unroll
        for (int half = 0; half < 2; half++) {
            float v = rsum[mf][half];
            v += __shfl_xor_sync(0xffffffffu, v, 1);
            v += __shfl_xor_sync(0xffffffffu, v, 2);
            if ((lane & 3) == 0) {
                int row = mrow0 + mf * 16 + half * 8 + r_in;
                if (row < LDIM) atomicAdd(&g_rowZ[b * LDIM + row], v);
            }
        }
    #pragma unroll
    for (int nf = 0; nf < 4; nf++)
        #pragma unroll
        for (int p = 0; p < 2; p++) {
            float v = csum[nf][p];
            v += __shfl_xor_sync(0xffffffffu, v, 4);
            v += __shfl_xor_sync(0xffffffffu, v, 8);
            v += __shfl_xor_sync(0xffffffffu, v, 16);
            if (lane < 4) {
                int col = ncol0 + nf * 8 + (lane & 3) * 2 + p;
                if (col < SDIM) atomicAdd(&g_colZ[b * SDIM + col], v);
            }
        }
}

// ---------------- K_conf: conf = e^2/(rowZ*colZ), colMax, candidate bitmask ----------------
#define CSLOT 3
#define RPB 8
#define CTHREADS 512
__global__ void __launch_bounds__(CTHREADS, 2) conf_kernel(float* __restrict__ out)
{
    const int b    = blockIdx.y;
    const int lc   = blockIdx.x;
    const int tid  = threadIdx.x;
    const int lane = tid & 31;
    const int bi0  = b * LDIM + lc * RPB;

    float4 colInv[CSLOT], cmax[CSLOT];
    u32 bnib = 0;
    #pragma unroll
    for (int j = 0; j < CSLOT; j++) {
        int s4 = tid + j * CTHREADS;
        if (s4 < 1200) {
            colInv[j] = *(const float4*)(g_colZ + b * SDIM + s4 * 4);
            colInv[j].x = 1.f / colInv[j].x;
            colInv[j].y = 1.f / colInv[j].y;
            colInv[j].z = 1.f / colInv[j].z;
            colInv[j].w = 1.f / colInv[j].w;
            u32 nib = 0;
            #pragma unroll
            for (int k = 0; k < 4; k++) {
                int s = s4 * 4 + k;
                int sh = s / 80, sw = s % 80;
                if (sh >= 2 && sh < 58 && sw >= 2 && sw < 78) nib |= (1u << k);
            }
            bnib |= nib << (4 * j);
        } else {
            colInv[j] = make_float4(0.f, 0.f, 0.f, 0.f);
        }
        cmax[j] = make_float4(0.f, 0.f, 0.f, 0.f);
    }

    float4 rz0 = *(const float4*)(g_rowZ + bi0);
    float4 rz1 = *(const float4*)(g_rowZ + bi0 + 4);
    float rowInvA[RPB] = { 1.f/rz0.x, 1.f/rz0.y, 1.f/rz0.z, 1.f/rz0.w,
                           1.f/rz1.x, 1.f/rz1.y, 1.f/rz1.z, 1.f/rz1.w };

    uint2 ecur[CSLOT], enext[CSLOT];
    {
        const uint2* er = (const uint2*)(g_sim + (size_t)bi0 * SDIM);
        #pragma unroll
        for (int j = 0; j < CSLOT; j++) {
            int s4 = tid + j * CTHREADS;
            ecur[j] = (s4 < 1200) ? __ldcs(er + s4) : make_uint2(0u, 0u);
        }
    }

    for (int r = 0; r < RPB; r++) {
        if (r < RPB - 1) {
            const uint2* er = (const uint2*)(g_sim + (size_t)(bi0 + r + 1) * SDIM);
            #pragma unroll
            for (int j = 0; j < CSLOT; j++) {
                int s4 = tid + j * CTHREADS;
                enext[j] = (s4 < 1200) ? __ldcs(er + s4) : make_uint2(0u, 0u);
            }
        }
        int l  = lc * RPB + r;
        int bi = bi0 + r;
        float rowInv = rowInvA[r];
        int lh = l / 80, lw = l % 80;
        bool lval = (lh >= 2) && (lh < 58) && (lw >= 2) && (lw < 78);
        float4* orow = (float4*)(out + (size_t)bi * SDIM);
        u32* mrow = g_mask + (size_t)bi * 152;
        #pragma unroll
        for (int j = 0; j < CSLOT; j++) {
            int s4 = tid + j * CTHREADS;
            u32 nib = 0;
            if (s4 < 1200) {
                __half2 h01, h23;
                memcpy(&h01, &ecur[j].x, 4);
                memcpy(&h23, &ecur[j].y, 4);
                float2 e01 = __half22float2(h01);
                float2 e23 = __half22float2(h23);
                float4 c;
                c.x = e01.x * e01.x * rowInv * colInv[j].x;
                c.y = e01.y * e01.y * rowInv * colInv[j].y;
                c.z = e23.x * e23.x * rowInv * colInv[j].z;
                c.w = e23.y * e23.y * rowInv * colInv[j].w;
                __stcs(orow + s4, c);
                cmax[j].x = fmaxf(cmax[j].x, c.x);
                cmax[j].y = fmaxf(cmax[j].y, c.y);
                cmax[j].z = fmaxf(cmax[j].z, c.z);
                cmax[j].w = fmaxf(cmax[j].w, c.w);
                if (lval) {
                    if (c.x > 0.2f) nib |= 1u;
                    if (c.y > 0.2f) nib |= 2u;
                    if (c.z > 0.2f) nib |= 4u;
                    if (c.w > 0.2f) nib |= 8u;
                    nib &= (bnib >> (4 * j)) & 15u;
                }
            }
            u32 v = nib << ((lane & 7) * 4);
            v |= __shfl_xor_sync(0xffffffffu, v, 1);
            v |= __shfl_xor_sync(0xffffffffu, v, 2);
            v |= __shfl_xor_sync(0xffffffffu, v, 4);
            if ((lane & 7) == 0) {
                int w = (tid + j * CTHREADS) >> 3;
                if (w < 150 && (tid + j * CTHREADS) < 1200) mrow[w] = v;
            }
        }
        #pragma unroll
        for (int j = 0; j < CSLOT; j++) ecur[j] = enext[j];
    }
    #pragma unroll
    for (int j = 0; j < CSLOT; j++) {
        int s4 = tid + j * CTHREADS;
        if (s4 < 1200) {
            u32* cm = g_colMax + b * SDIM + s4 * 4;
            atomicMax(cm + 0, __float_as_uint(cmax[j].x));
            atomicMax(cm + 1, __float_as_uint(cmax[j].y));
            atomicMax(cm + 2, __float_as_uint(cmax[j].z));
            atomicMax(cm + 3, __float_as_uint(cmax[j].w));
        }
    }
}

// ---------------- K_match: one warp per row, scans candidate bitmask ----------------
__global__ void __launch_bounds__(256) match_kernel(float* __restrict__ out)
{
    const int wid  = threadIdx.x >> 5;
    const int lane = threadIdx.x & 31;
    const int bi   = blockIdx.x * 8 + wid;
    const int b    = bi / LDIM;

    const u32* mrow = g_mask + (size_t)bi * 152;
    u64 best = 0ull;
    for (int w = lane; w < 150; w += 32) {
        u32 m = mrow[w];
        while (m) {
            int bit = __ffs(m) - 1;
            m &= m - 1;
            int s = (w << 5) + bit;
            u64 key = ((u64)g_colMax[b * SDIM + s] << 32)
                    | (u64)(0xFFFFFFFFu - (u32)s);
            if (key > best) best = key;
        }
    }
    #pragma unroll
    for (int o = 16; o; o >>= 1) {
        u64 v = __shfl_xor_sync(0xffffffffu, best, o);
        if (v > best) best = v;
    }
    if (lane == 0) {
        float match = 0.f, sid = 0.f, mc = 0.f, kx = 0.f, ky = 0.f;
        if (best) {
            int s = (int)(0xFFFFFFFFu - (u32)(best & 0xFFFFFFFFull));
            match = 1.f;
            sid = (float)s;
            mc = out[(size_t)bi * SDIM + s];
            kx = (float)(s % 80) * 8.f;
            ky = (float)(s / 80) * 8.f;
        }
        out[OFF_MATCH + bi] = match;
        out[OFF_SID   + bi] = sid;
        out[OFF_MCONF + bi] = mc;
        out[OFF_MK1 + (size_t)bi * 2]     = kx;
        out[OFF_MK1 + (size_t)bi * 2 + 1] = ky;
    }
}

extern "C" void kernel_launch(void* const* d_in, const int* in_sizes, int n_in,
                              void* d_out, int out_size)
{
    const float* f0 = (const float*)d_in[0];
    const float* f1 = (const float*)d_in[1];
    float* out = (float*)d_out;
    const bool full = ((unsigned)out_size >= TOTAL_OUT);

    const int TOT = (BATCH * LDIM * CDIM) / 4;
    prep_kernel<<<(TOT + 255) / 256, 256>>>(f0, f1, out, full ? 1 : 0);

    dim3 gg((SDIM + 127) / 128, (LDIM + 127) / 128, BATCH);
    gemm_kernel<<<gg, 256>>>();

    dim3 gc(LDIM / RPB, BATCH);
    conf_kernel<<<gc, CTHREADS>>>(out);

    if (full) match_kernel<<<(BATCH * LDIM) / 8, 256>>>(out);
}

// round 16
// speedup vs baseline: 1.1898x; 1.0449x over previous
#include <cuda_runtime.h>
#include <cuda_fp16.h>
#include <cstdint>
#include <cstring>

typedef unsigned long long u64;
typedef unsigned int u32;

#define BATCH 4
#define LDIM 4800
#define SDIM 4800
#define CDIM 256
#define KPK 256
#define EXP_SCALE (1.442695041f/25.6f)  // log2(e)/(C*TEMP)

// output layout (float32, concatenated reference outputs)
#define OFF_MATCH 92160000u
#define OFF_SID   92179200u
#define OFF_MCONF 92198400u
#define OFF_MK0   92217600u
#define OFF_MK1   92227200u
#define TOTAL_OUT 92265600u

// ---------------- device scratch ----------------
__device__ __half g_sim[(size_t)BATCH * LDIM * SDIM];  // exp(sim) in fp16
__device__ __half g_a[(size_t)BATCH * LDIM * KPK];
__device__ __half g_b[(size_t)BATCH * SDIM * KPK];
__device__ float g_rowZ[BATCH * LDIM];
__device__ float g_colZ[BATCH * SDIM];
__device__ u32   g_colMax[BATCH * SDIM];
__device__ u32   g_mask[(size_t)BATCH * LDIM * 152];   // 150 words + pad per row

// ---------------- helpers ----------------
__device__ __forceinline__ u32 h2_bits(__half2 h) {
    u32 r; memcpy(&r, &h, 4); return r;
}
__device__ __forceinline__ u32 smem_u32(const void* p) {
    u32 a;
    asm("{ .reg .u64 t; cvta.to.shared.u64 t, %1; cvt.u32.u64 %0, t; }"
        : "=r"(a) : "l"(p));
    return a;
}
__device__ __forceinline__ void cpasync16(u32 dst, const void* src) {
    asm volatile("cp.async.cg.shared.global [%0], [%1], 16;"
                 :: "r"(dst), "l"(src) : "memory");
}
#define CP_COMMIT() asm volatile("cp.async.commit_group;" ::: "memory")
#define CP_WAIT(n)  asm volatile("cp.async.wait_group %0;" :: "n"(n) : "memory")

__device__ __forceinline__ void ldsm4(u32& r0, u32& r1, u32& r2, u32& r3, u32 addr) {
    asm volatile("ldmatrix.sync.aligned.m8n8.x4.shared.b16 {%0,%1,%2,%3}, [%4];"
                 : "=r"(r0), "=r"(r1), "=r"(r2), "=r"(r3) : "r"(addr));
}
__device__ __forceinline__ void mma16816(float* d, const u32* a, const u32* b) {
    asm volatile(
        "mma.sync.aligned.m16n8k16.row.col.f32.f16.f16.f32 "
        "{%0,%1,%2,%3}, {%4,%5,%6,%7}, {%8,%9}, {%0,%1,%2,%3};"
        : "+f"(d[0]), "+f"(d[1]), "+f"(d[2]), "+f"(d[3])
        : "r"(a[0]), "r"(a[1]), "r"(a[2]), "r"(a[3]), "r"(b[0]), "r"(b[1]));
}
__device__ __forceinline__ float ex2f(float x) {
    float r; asm("ex2.approx.f32 %0, %1;" : "=f"(r) : "f"(x)); return r;
}

// ---------------- K_prep: fp32 -> fp16 ; fused init ----------------
__global__ void prep_kernel(const float* __restrict__ f0,
                            const float* __restrict__ f1,
                            float* __restrict__ out, int full)
{
    int idx = blockIdx.x * blockDim.x + threadIdx.x;

    if (idx < BATCH * SDIM) { g_colZ[idx] = 0.f; g_colMax[idx] = 0u; }
    if (idx < BATCH * LDIM) g_rowZ[idx] = 0.f;
    if (full && idx < LDIM) {
        out[OFF_MK0 + 2 * idx]     = (float)(idx % 80) * 8.f;
        out[OFF_MK0 + 2 * idx + 1] = (float)(idx / 80) * 8.f;
    }

    const int TOT = (BATCH * LDIM * CDIM) / 4;
    if (idx >= TOT) return;
    float4 x0 = *(const float4*)(f0 + idx * 4);
    float4 x1 = *(const float4*)(f1 + idx * 4);
    u32 a01 = h2_bits(__floats2half2_rn(x0.x, x0.y));
    u32 a23 = h2_bits(__floats2half2_rn(x0.z, x0.w));
    u32 b01 = h2_bits(__floats2half2_rn(x1.x, x1.y));
    u32 b23 = h2_bits(__floats2half2_rn(x1.z, x1.w));
    *(uint2*)(g_a + idx * 4) = make_uint2(a01, a23);
    *(uint2*)(g_b + idx * 4) = make_uint2(b01, b23);
}

// ---------------- K_gemm: 2-stage BK=32 + fused exp/sums + staged coalesced store ----
#define PADB 80
#define NCH  8
#define STGW 136   // staging row stride in halves (272B, conflict-free)

__global__ void __launch_bounds__(256, 2) gemm_kernel()
{
    // 40960 B: mainloop double buffers; reused as 128x136-half e-staging (34816 B)
    __shared__ __align__(16) char sm[2 * 128 * PADB * 2];

    const int tid  = threadIdx.x;
    const int wid  = tid >> 5;
    const int lane = tid & 31;
    const int b    = blockIdx.z;
    const int l0   = blockIdx.y * 128;
    const int s0   = blockIdx.x * 128;
    const int wm   = wid & 1;
    const int wn   = wid >> 1;

    const __half* gA = g_a + (size_t)b * LDIM * KPK;
    const __half* gB = g_b + (size_t)b * SDIM * KPK;
    u32 base = smem_u32(sm);
    u32 aA[2] = { base,               base + 128 * PADB };
    u32 aB[2] = { base + 2*128*PADB,  base + 3*128*PADB };

    const int lrow0 = tid >> 2;
    const int lpart = tid & 3;

    float acc[4][4][4];
    #pragma unroll
    for (int i = 0; i < 4; i++)
        #pragma unroll
        for (int j = 0; j < 4; j++)
            #pragma unroll
            for (int v = 0; v < 4; v++) acc[i][j][v] = 0.f;

    auto load_chunk = [&](int ch, int buf) {
        #pragma unroll
        for (int i = 0; i < 2; i++) {
            int row = lrow0 + i * 64;
            u32 off = (u32)(row * PADB + lpart * 16);
            int gl = l0 + row; if (gl > LDIM - 1) gl = LDIM - 1;
            cpasync16(aA[buf] + off, gA + (size_t)gl * KPK + ch * 32 + lpart * 8);
            int gs = s0 + row; if (gs > SDIM - 1) gs = SDIM - 1;
            cpasync16(aB[buf] + off, gB + (size_t)gs * KPK + ch * 32 + lpart * 8);
        }
        CP_COMMIT();
    };

    load_chunk(0, 0);

    const int rsel = (lane & 7) + ((lane >> 3) & 1) * 8;
    const int ksel = lane >> 4;

    #pragma unroll 1
    for (int ch = 0; ch < NCH; ch++) {
        if (ch < NCH - 1) { load_chunk(ch + 1, (ch + 1) & 1); CP_WAIT(1); }
        else              { CP_WAIT(0); }
        __syncthreads();
        u32 bufA = aA[ch & 1], bufB = aB[ch & 1];

        #pragma unroll
        for (int kk = 0; kk < 2; kk++) {
            u32 a[4][4], bb[4][2];
            #pragma unroll
            for (int mf = 0; mf < 4; mf++) {
                int row = wm * 64 + mf * 16 + rsel;
                ldsm4(a[mf][0], a[mf][1], a[mf][2], a[mf][3],
                      bufA + (u32)(row * PADB + kk * 32 + ksel * 16));
            }
            #pragma unroll
            for (int np = 0; np < 2; np++) {
                int row = wn * 32 + np * 16 + rsel;
                u32 r0, r1, r2, r3;
                ldsm4(r0, r1, r2, r3,
                      bufB + (u32)(row * PADB + kk * 32 + ksel * 16));
                bb[np * 2][0]     = r0; bb[np * 2][1]     = r2;
                bb[np * 2 + 1][0] = r1; bb[np * 2 + 1][1] = r3;
            }
            #pragma unroll
            for (int mf = 0; mf < 4; mf++)
                #pragma unroll
                for (int nf = 0; nf < 4; nf++)
                    mma16816(acc[mf][nf], a[mf], bb[nf]);
        }
        __syncthreads();
    }

    // ---- fused epilogue: e = exp fp32, stage fp16 in smem; sums AFTER store issue ----
    const int mrow0 = l0 + wm * 64;
    const int ncol0 = s0 + wn * 32;
    const int r_in  = lane >> 2;
    const int c_in  = (lane & 3) * 2;
    __half* stg = (__half*)sm;   // 128 x STGW halves

    float rsum[4][2];
    float csum[4][2];
    #pragma unroll
    for (int i = 0; i < 4; i++) { rsum[i][0] = rsum[i][1] = 0.f; csum[i][0] = csum[i][1] = 0.f; }

    #pragma unroll
    for (int mf = 0; mf < 4; mf++) {
        #pragma unroll
        for (int half = 0; half < 2; half++) {
            int lrow = wm * 64 + mf * 16 + half * 8 + r_in;   // local 0..127
            int row  = l0 + lrow;
            bool rok = row < LDIM;
            #pragma unroll
            for (int nf = 0; nf < 4; nf++) {
                int col = ncol0 + nf * 8 + c_in;
                bool ok = rok && (col < SDIM);
                float e0 = ok ? ex2f(acc[mf][nf][half * 2]     * EXP_SCALE) : 0.f;
                float e1 = ok ? ex2f(acc[mf][nf][half * 2 + 1] * EXP_SCALE) : 0.f;
                *(__half2*)(stg + lrow * STGW + wn * 32 + nf * 8 + c_in) =
                    __floats2half2_rn(e0, e1);
                rsum[mf][half] += e0 + e1;
                csum[nf][0] += e0;
                csum[nf][1] += e1;
            }
        }
    }
    __syncthreads();
    // copy-out stores FIRST (fire-and-forget), reductions overlap the drain
    {
        const int crow = tid >> 4;          // 0..15
        const int cchk = tid & 15;          // 0..15
        #pragma unroll
        for (int it = 0; it < 8; it++) {
            int lrow = it * 16 + crow;
            int grow = l0 + lrow;
            int gcol = s0 + cchk * 8;
            uint4 v = *(const uint4*)(stg + lrow * STGW + cchk * 8);
            if (grow < LDIM && gcol + 7 < SDIM)
                __stcs((uint4*)(g_sim + ((size_t)b * LDIM + grow) * SDIM + gcol), v);
        }
    }
    // reductions after store issue
    #pragma unroll
    for (int mf = 0; mf < 4; mf++)
        #pragma unroll
        for (int half = 0; half < 2; half++) {
            float v = rsum[mf][half];
            v += __shfl_xor_sync(0xffffffffu, v, 1);
            v += __shfl_xor_sync(0xffffffffu, v, 2);
            if ((lane & 3) == 0) {
                int row = mrow0 + mf * 16 + half * 8 + r_in;
                if (row < LDIM) atomicAdd(&g_rowZ[b * LDIM + row], v);
            }
        }
    #pragma unroll
    for (int nf = 0; nf < 4; nf++)
        #pragma unroll
        for (int p = 0; p < 2; p++) {
            float v = csum[nf][p];
            v += __shfl_xor_sync(0xffffffffu, v, 4);
            v += __shfl_xor_sync(0xffffffffu, v, 8);
            v += __shfl_xor_sync(0xffffffffu, v, 16);
            if (lane < 4) {
                int col = ncol0 + nf * 8 + (lane & 3) * 2 + p;
                if (col < SDIM) atomicAdd(&g_colZ[b * SDIM + col], v);
            }
        }
}

// ---------------- K_conf: conf = e^2/(rowZ*colZ), colMax, candidate bitmask ----------------
// RPB=16: amortize colInv/border prologue over twice the rows; 1200 blocks.
#define CSLOT 3
#define RPB 16
#define CTHREADS 512
__global__ void __launch_bounds__(CTHREADS, 2) conf_kernel(float* __restrict__ out)
{
    const int b    = blockIdx.y;
    const int lc   = blockIdx.x;
    const int tid  = threadIdx.x;
    const int lane = tid & 31;
    const int bi0  = b * LDIM + lc * RPB;

    float4 colInv[CSLOT], cmax[CSLOT];
    u32 bnib = 0;
    #pragma unroll
    for (int j = 0; j < CSLOT; j++) {
        int s4 = tid + j * CTHREADS;
        if (s4 < 1200) {
            colInv[j] = *(const float4*)(g_colZ + b * SDIM + s4 * 4);
            colInv[j].x = 1.f / colInv[j].x;
            colInv[j].y = 1.f / colInv[j].y;
            colInv[j].z = 1.f / colInv[j].z;
            colInv[j].w = 1.f / colInv[j].w;
            u32 nib = 0;
            #pragma unroll
            for (int k = 0; k < 4; k++) {
                int s = s4 * 4 + k;
                int sh = s / 80, sw = s % 80;
                if (sh >= 2 && sh < 58 && sw >= 2 && sw < 78) nib |= (1u << k);
            }
            bnib |= nib << (4 * j);
        } else {
            colInv[j] = make_float4(0.f, 0.f, 0.f, 0.f);
        }
        cmax[j] = make_float4(0.f, 0.f, 0.f, 0.f);
    }

    float rowInvA[RPB];
    #pragma unroll
    for (int q = 0; q < RPB / 4; q++) {
        float4 rz = *(const float4*)(g_rowZ + bi0 + q * 4);
        rowInvA[q * 4 + 0] = 1.f / rz.x;
        rowInvA[q * 4 + 1] = 1.f / rz.y;
        rowInvA[q * 4 + 2] = 1.f / rz.z;
        rowInvA[q * 4 + 3] = 1.f / rz.w;
    }

    uint2 ecur[CSLOT], enext[CSLOT];
    {
        const uint2* er = (const uint2*)(g_sim + (size_t)bi0 * SDIM);
        #pragma unroll
        for (int j = 0; j < CSLOT; j++) {
            int s4 = tid + j * CTHREADS;
            ecur[j] = (s4 < 1200) ? __ldcs(er + s4) : make_uint2(0u, 0u);
        }
    }

    for (int r = 0; r < RPB; r++) {
        if (r < RPB - 1) {
            const uint2* er = (const uint2*)(g_sim + (size_t)(bi0 + r + 1) * SDIM);
            #pragma unroll
            for (int j = 0; j < CSLOT; j++) {
                int s4 = tid + j * CTHREADS;
                enext[j] = (s4 < 1200) ? __ldcs(er + s4) : make_uint2(0u, 0u);
            }
        }
        int l  = lc * RPB + r;
        int bi = bi0 + r;
        float rowInv = rowInvA[r];
        int lh = l / 80, lw = l % 80;
        bool lval = (lh >= 2) && (lh < 58) && (lw >= 2) && (lw < 78);
        float4* orow = (float4*)(out + (size_t)bi * SDIM);
        u32* mrow = g_mask + (size_t)bi * 152;
        #pragma unroll
        for (int j = 0; j < CSLOT; j++) {
            int s4 = tid + j * CTHREADS;
            u32 nib = 0;
            if (s4 < 1200) {
                __half2 h01, h23;
                memcpy(&h01, &ecur[j].x, 4);
                memcpy(&h23, &ecur[j].y, 4);
                float2 e01 = __half22float2(h01);
                float2 e23 = __half22float2(h23);
                float4 c;
                c.x = e01.x * e01.x * rowInv * colInv[j].x;
                c.y = e01.y * e01.y * rowInv * colInv[j].y;
                c.z = e23.x * e23.x * rowInv * colInv[j].z;
                c.w = e23.y * e23.y * rowInv * colInv[j].w;
                __stcs(orow + s4, c);
                cmax[j].x = fmaxf(cmax[j].x, c.x);
                cmax[j].y = fmaxf(cmax[j].y, c.y);
                cmax[j].z = fmaxf(cmax[j].z, c.z);
                cmax[j].w = fmaxf(cmax[j].w, c.w);
                if (lval) {
                    if (c.x > 0.2f) nib |= 1u;
                    if (c.y > 0.2f) nib |= 2u;
                    if (c.z > 0.2f) nib |= 4u;
                    if (c.w > 0.2f) nib |= 8u;
                    nib &= (bnib >> (4 * j)) & 15u;
                }
            }
            u32 v = nib << ((lane & 7) * 4);
            v |= __shfl_xor_sync(0xffffffffu, v, 1);
            v |= __shfl_xor_sync(0xffffffffu, v, 2);
            v |= __shfl_xor_sync(0xffffffffu, v, 4);
            if ((lane & 7) == 0) {
                int w = (tid + j * CTHREADS) >> 3;
                if (w < 150 && (tid + j * CTHREADS) < 1200) mrow[w] = v;
            }
        }
        #pragma unroll
        for (int j = 0; j < CSLOT; j++) ecur[j] = enext[j];
    }
    #pragma unroll
    for (int j = 0; j < CSLOT; j++) {
        int s4 = tid + j * CTHREADS;
        if (s4 < 1200) {
            u32* cm = g_colMax + b * SDIM + s4 * 4;
            atomicMax(cm + 0, __float_as_uint(cmax[j].x));
            atomicMax(cm + 1, __float_as_uint(cmax[j].y));
            atomicMax(cm + 2, __float_as_uint(cmax[j].z));
            atomicMax(cm + 3, __float_as_uint(cmax[j].w));
        }
    }
}

// ---------------- K_match: one warp per row, scans candidate bitmask ----------------
__global__ void __launch_bounds__(256) match_kernel(float* __restrict__ out)
{
    const int wid  = threadIdx.x >> 5;
    const int lane = threadIdx.x & 31;
    const int bi   = blockIdx.x * 8 + wid;
    const int b    = bi / LDIM;

    const u32* mrow = g_mask + (size_t)bi * 152;
    u64 best = 0ull;
    for (int w = lane; w < 150; w += 32) {
        u32 m = mrow[w];
        while (m) {
            int bit = __ffs(m) - 1;
            m &= m - 1;
            int s = (w << 5) + bit;
            u64 key = ((u64)g_colMax[b * SDIM + s] << 32)
                    | (u64)(0xFFFFFFFFu - (u32)s);
            if (key > best) best = key;
        }
    }
    #pragma unroll
    for (int o = 16; o; o >>= 1) {
        u64 v = __shfl_xor_sync(0xffffffffu, best, o);
        if (v > best) best = v;
    }
    if (lane == 0) {
        float match = 0.f, sid = 0.f, mc = 0.f, kx = 0.f, ky = 0.f;
        if (best) {
            int s = (int)(0xFFFFFFFFu - (u32)(best & 0xFFFFFFFFull));
            match = 1.f;
            sid = (float)s;
            mc = out[(size_t)bi * SDIM + s];
            kx = (float)(s % 80) * 8.f;
            ky = (float)(s / 80) * 8.f;
        }
        out[OFF_MATCH + bi] = match;
        out[OFF_SID   + bi] = sid;
        out[OFF_MCONF + bi] = mc;
        out[OFF_MK1 + (size_t)bi * 2]     = kx;
        out[OFF_MK1 + (size_t)bi * 2 + 1] = ky;
    }
}

extern "C" void kernel_launch(void* const* d_in, const int* in_sizes, int n_in,
                              void* d_out, int out_size)
{
    const float* f0 = (const float*)d_in[0];
    const float* f1 = (const float*)d_in[1];
    float* out = (float*)d_out;
    const bool full = ((unsigned)out_size >= TOTAL_OUT);

    const int TOT = (BATCH * LDIM * CDIM) / 4;
    prep_kernel<<<(TOT + 255) / 256, 256>>>(f0, f1, out, full ? 1 : 0);

    dim3 gg((SDIM + 127) / 128, (LDIM + 127) / 128, BATCH);
    gemm_kernel<<<gg, 256>>>();

    dim3 gc(LDIM / RPB, BATCH);
    conf_kernel<<<gc, CTHREADS>>>(out);

    if (full) match_kernel<<<(BATCH * LDIM) / 8, 256>>>(out);
}

// round 17
// speedup vs baseline: 1.2128x; 1.0193x over previous
#include <cuda_runtime.h>
#include <cuda_fp16.h>
#include <cstdint>
#include <cstring>

typedef unsigned long long u64;
typedef unsigned int u32;

#define BATCH 4
#define LDIM 4800
#define SDIM 4800
#define CDIM 256
#define KPK 256
#define EXP_SCALE (1.442695041f/25.6f)  // log2(e)/(C*TEMP)

// output layout (float32, concatenated reference outputs)
#define OFF_MATCH 92160000u
#define OFF_SID   92179200u
#define OFF_MCONF 92198400u
#define OFF_MK0   92217600u
#define OFF_MK1   92227200u
#define TOTAL_OUT 92265600u

// ---------------- device scratch ----------------
__device__ __half g_sim[(size_t)BATCH * LDIM * SDIM];  // exp(sim) in fp16
__device__ __half g_a[(size_t)BATCH * LDIM * KPK];
__device__ __half g_b[(size_t)BATCH * SDIM * KPK];
__device__ float g_rowZ[BATCH * LDIM];
__device__ float g_colZ[BATCH * SDIM];
__device__ u32   g_colMax[BATCH * SDIM];
__device__ u32   g_mask[(size_t)BATCH * LDIM * 152];   // 150 words + pad per row

// ---------------- helpers ----------------
__device__ __forceinline__ u32 h2_bits(__half2 h) {
    u32 r; memcpy(&r, &h, 4); return r;
}
__device__ __forceinline__ u32 smem_u32(const void* p) {
    u32 a;
    asm("{ .reg .u64 t; cvta.to.shared.u64 t, %1; cvt.u32.u64 %0, t; }"
        : "=r"(a) : "l"(p));
    return a;
}
__device__ __forceinline__ void cpasync16(u32 dst, const void* src) {
    asm volatile("cp.async.cg.shared.global [%0], [%1], 16;"
                 :: "r"(dst), "l"(src) : "memory");
}
#define CP_COMMIT() asm volatile("cp.async.commit_group;" ::: "memory")
#define CP_WAIT(n)  asm volatile("cp.async.wait_group %0;" :: "n"(n) : "memory")

__device__ __forceinline__ void ldsm4(u32& r0, u32& r1, u32& r2, u32& r3, u32 addr) {
    asm volatile("ldmatrix.sync.aligned.m8n8.x4.shared.b16 {%0,%1,%2,%3}, [%4];"
                 : "=r"(r0), "=r"(r1), "=r"(r2), "=r"(r3) : "r"(addr));
}
__device__ __forceinline__ void mma16816(float* d, const u32* a, const u32* b) {
    asm volatile(
        "mma.sync.aligned.m16n8k16.row.col.f32.f16.f16.f32 "
        "{%0,%1,%2,%3}, {%4,%5,%6,%7}, {%8,%9}, {%0,%1,%2,%3};"
        : "+f"(d[0]), "+f"(d[1]), "+f"(d[2]), "+f"(d[3])
        : "r"(a[0]), "r"(a[1]), "r"(a[2]), "r"(a[3]), "r"(b[0]), "r"(b[1]));
}
__device__ __forceinline__ float ex2f(float x) {
    float r; asm("ex2.approx.f32 %0, %1;" : "=f"(r) : "f"(x)); return r;
}

// ---------------- K_prep: fp32 -> fp16 ; fused init ----------------
__global__ void prep_kernel(const float* __restrict__ f0,
                            const float* __restrict__ f1,
                            float* __restrict__ out, int full)
{
    int idx = blockIdx.x * blockDim.x + threadIdx.x;

    if (idx < BATCH * SDIM) { g_colZ[idx] = 0.f; g_colMax[idx] = 0u; }
    if (idx < BATCH * LDIM) g_rowZ[idx] = 0.f;
    if (full && idx < LDIM) {
        out[OFF_MK0 + 2 * idx]     = (float)(idx % 80) * 8.f;
        out[OFF_MK0 + 2 * idx + 1] = (float)(idx / 80) * 8.f;
    }

    const int TOT = (BATCH * LDIM * CDIM) / 4;
    if (idx >= TOT) return;
    float4 x0 = *(const float4*)(f0 + idx * 4);
    float4 x1 = *(const float4*)(f1 + idx * 4);
    u32 a01 = h2_bits(__floats2half2_rn(x0.x, x0.y));
    u32 a23 = h2_bits(__floats2half2_rn(x0.z, x0.w));
    u32 b01 = h2_bits(__floats2half2_rn(x1.x, x1.y));
    u32 b23 = h2_bits(__floats2half2_rn(x1.z, x1.w));
    *(uint2*)(g_a + idx * 4) = make_uint2(a01, a23);
    *(uint2*)(g_b + idx * 4) = make_uint2(b01, b23);
}

// ---------------- K_invert: rowZ/colZ -> reciprocals (in place) ----------------
__global__ void invert_kernel()
{
    int idx = blockIdx.x * blockDim.x + threadIdx.x;
    if (idx < BATCH * LDIM) g_rowZ[idx] = 1.f / g_rowZ[idx];
    if (idx < BATCH * SDIM) g_colZ[idx] = 1.f / g_colZ[idx];
}

// ---------------- K_gemm: 2-stage BK=32 + fused exp/sums + staged coalesced store ----
#define PADB 80
#define NCH  8
#define STGW 136   // staging row stride in halves (272B, conflict-free)

__global__ void __launch_bounds__(256, 2) gemm_kernel()
{
    // 40960 B: mainloop double buffers; reused as 128x136-half e-staging (34816 B)
    __shared__ __align__(16) char sm[2 * 128 * PADB * 2];

    const int tid  = threadIdx.x;
    const int wid  = tid >> 5;
    const int lane = tid & 31;
    const int b    = blockIdx.z;
    const int l0   = blockIdx.y * 128;
    const int s0   = blockIdx.x * 128;
    const int wm   = wid & 1;
    const int wn   = wid >> 1;

    const __half* gA = g_a + (size_t)b * LDIM * KPK;
    const __half* gB = g_b + (size_t)b * SDIM * KPK;
    u32 base = smem_u32(sm);
    u32 aA[2] = { base,               base + 128 * PADB };
    u32 aB[2] = { base + 2*128*PADB,  base + 3*128*PADB };

    const int lrow0 = tid >> 2;
    const int lpart = tid & 3;

    float acc[4][4][4];
    #pragma unroll
    for (int i = 0; i < 4; i++)
        #pragma unroll
        for (int j = 0; j < 4; j++)
            #pragma unroll
            for (int v = 0; v < 4; v++) acc[i][j][v] = 0.f;

    auto load_chunk = [&](int ch, int buf) {
        #pragma unroll
        for (int i = 0; i < 2; i++) {
            int row = lrow0 + i * 64;
            u32 off = (u32)(row * PADB + lpart * 16);
            int gl = l0 + row; if (gl > LDIM - 1) gl = LDIM - 1;
            cpasync16(aA[buf] + off, gA + (size_t)gl * KPK + ch * 32 + lpart * 8);
            int gs = s0 + row; if (gs > SDIM - 1) gs = SDIM - 1;
            cpasync16(aB[buf] + off, gB + (size_t)gs * KPK + ch * 32 + lpart * 8);
        }
        CP_COMMIT();
    };

    load_chunk(0, 0);

    const int rsel = (lane & 7) + ((lane >> 3) & 1) * 8;
    const int ksel = lane >> 4;

    #pragma unroll 1
    for (int ch = 0; ch < NCH; ch++) {
        if (ch < NCH - 1) { load_chunk(ch + 1, (ch + 1) & 1); CP_WAIT(1); }
        else              { CP_WAIT(0); }
        __syncthreads();
        u32 bufA = aA[ch & 1], bufB = aB[ch & 1];

        #pragma unroll
        for (int kk = 0; kk < 2; kk++) {
            u32 a[4][4], bb[4][2];
            #pragma unroll
            for (int mf = 0; mf < 4; mf++) {
                int row = wm * 64 + mf * 16 + rsel;
                ldsm4(a[mf][0], a[mf][1], a[mf][2], a[mf][3],
                      bufA + (u32)(row * PADB + kk * 32 + ksel * 16));
            }
            #pragma unroll
            for (int np = 0; np < 2; np++) {
                int row = wn * 32 + np * 16 + rsel;
                u32 r0, r1, r2, r3;
                ldsm4(r0, r1, r2, r3,
                      bufB + (u32)(row * PADB + kk * 32 + ksel * 16));
                bb[np * 2][0]     = r0; bb[np * 2][1]     = r2;
                bb[np * 2 + 1][0] = r1; bb[np * 2 + 1][1] = r3;
            }
            #pragma unroll
            for (int mf = 0; mf < 4; mf++)
                #pragma unroll
                for (int nf = 0; nf < 4; nf++)
                    mma16816(acc[mf][nf], a[mf], bb[nf]);
        }
        __syncthreads();
    }

    // ---- fused epilogue: e = exp fp32, stage fp16 in smem; sums AFTER store issue ----
    const int mrow0 = l0 + wm * 64;
    const int ncol0 = s0 + wn * 32;
    const int r_in  = lane >> 2;
    const int c_in  = (lane & 3) * 2;
    __half* stg = (__half*)sm;   // 128 x STGW halves

    float rsum[4][2];
    float csum[4][2];
    #pragma unroll
    for (int i = 0; i < 4; i++) { rsum[i][0] = rsum[i][1] = 0.f; csum[i][0] = csum[i][1] = 0.f; }

    #pragma unroll
    for (int mf = 0; mf < 4; mf++) {
        #pragma unroll
        for (int half = 0; half < 2; half++) {
            int lrow = wm * 64 + mf * 16 + half * 8 + r_in;   // local 0..127
            int row  = l0 + lrow;
            bool rok = row < LDIM;
            #pragma unroll
            for (int nf = 0; nf < 4; nf++) {
                int col = ncol0 + nf * 8 + c_in;
                bool ok = rok && (col < SDIM);
                float e0 = ok ? ex2f(acc[mf][nf][half * 2]     * EXP_SCALE) : 0.f;
                float e1 = ok ? ex2f(acc[mf][nf][half * 2 + 1] * EXP_SCALE) : 0.f;
                *(__half2*)(stg + lrow * STGW + wn * 32 + nf * 8 + c_in) =
                    __floats2half2_rn(e0, e1);
                rsum[mf][half] += e0 + e1;
                csum[nf][0] += e0;
                csum[nf][1] += e1;
            }
        }
    }
    __syncthreads();
    // copy-out stores FIRST (fire-and-forget), reductions overlap the drain
    {
        const int crow = tid >> 4;          // 0..15
        const int cchk = tid & 15;          // 0..15
        #pragma unroll
        for (int it = 0; it < 8; it++) {
            int lrow = it * 16 + crow;
            int grow = l0 + lrow;
            int gcol = s0 + cchk * 8;
            uint4 v = *(const uint4*)(stg + lrow * STGW + cchk * 8);
            if (grow < LDIM && gcol + 7 < SDIM)
                __stcs((uint4*)(g_sim + ((size_t)b * LDIM + grow) * SDIM + gcol), v);
        }
    }
    // reductions after store issue
    #pragma unroll
    for (int mf = 0; mf < 4; mf++)
        #pragma unroll
        for (int half = 0; half < 2; half++) {
            float v = rsum[mf][half];
            v += __shfl_xor_sync(0xffffffffu, v, 1);
            v += __shfl_xor_sync(0xffffffffu, v, 2);
            if ((lane & 3) == 0) {
                int row = mrow0 + mf * 16 + half * 8 + r_in;
                if (row < LDIM) atomicAdd(&g_rowZ[b * LDIM + row], v);
            }
        }
    #pragma unroll
    for (int nf = 0; nf < 4; nf++)
        #pragma unroll
        for (int p = 0; p < 2; p++) {
            float v = csum[nf][p];
            v += __shfl_xor_sync(0xffffffffu, v, 4);
            v += __shfl_xor_sync(0xffffffffu, v, 8);
            v += __shfl_xor_sync(0xffffffffu, v, 16);
            if (lane < 4) {
                int col = ncol0 + nf * 8 + (lane & 3) * 2 + p;
                if (col < SDIM) atomicAdd(&g_colZ[b * SDIM + col], v);
            }
        }
}

// ---------------- K_conf: conf = e^2*rowInv*colInv, colMax, candidate bitmask ----------------
// RPB=32, 600 blocks; rowZ/colZ hold PRE-INVERTED values (invert_kernel).
#define CSLOT 3
#define RPB 32
#define CTHREADS 512
__global__ void __launch_bounds__(CTHREADS, 2) conf_kernel(float* __restrict__ out)
{
    const int b    = blockIdx.y;
    const int lc   = blockIdx.x;
    const int tid  = threadIdx.x;
    const int lane = tid & 31;
    const int bi0  = b * LDIM + lc * RPB;

    float4 colInv[CSLOT], cmax[CSLOT];
    u32 bnib = 0;
    #pragma unroll
    for (int j = 0; j < CSLOT; j++) {
        int s4 = tid + j * CTHREADS;
        if (s4 < 1200) {
            colInv[j] = *(const float4*)(g_colZ + b * SDIM + s4 * 4);  // pre-inverted
            u32 nib = 0;
            #pragma unroll
            for (int k = 0; k < 4; k++) {
                int s = s4 * 4 + k;
                int sh = s / 80, sw = s % 80;
                if (sh >= 2 && sh < 58 && sw >= 2 && sw < 78) nib |= (1u << k);
            }
            bnib |= nib << (4 * j);
        } else {
            colInv[j] = make_float4(0.f, 0.f, 0.f, 0.f);
        }
        cmax[j] = make_float4(0.f, 0.f, 0.f, 0.f);
    }

    uint2 ecur[CSLOT], enext[CSLOT];
    {
        const uint2* er = (const uint2*)(g_sim + (size_t)bi0 * SDIM);
        #pragma unroll
        for (int j = 0; j < CSLOT; j++) {
            int s4 = tid + j * CTHREADS;
            ecur[j] = (s4 < 1200) ? __ldcs(er + s4) : make_uint2(0u, 0u);
        }
    }

    #pragma unroll 1
    for (int rg = 0; rg < RPB / 8; rg++) {
        // load this group's 8 pre-inverted row normalizers
        float4 rz0 = *(const float4*)(g_rowZ + bi0 + rg * 8);
        float4 rz1 = *(const float4*)(g_rowZ + bi0 + rg * 8 + 4);
        float rowInvA[8] = { rz0.x, rz0.y, rz0.z, rz0.w,
                             rz1.x, rz1.y, rz1.z, rz1.w };
        #pragma unroll
        for (int rr = 0; rr < 8; rr++) {
            int r  = rg * 8 + rr;
            if (r < RPB - 1) {
                const uint2* er = (const uint2*)(g_sim + (size_t)(bi0 + r + 1) * SDIM);
                #pragma unroll
                for (int j = 0; j < CSLOT; j++) {
                    int s4 = tid + j * CTHREADS;
                    enext[j] = (s4 < 1200) ? __ldcs(er + s4) : make_uint2(0u, 0u);
                }
            }
            int l  = lc * RPB + r;
            int bi = bi0 + r;
            float rowInv = rowInvA[rr];
            int lh = l / 80, lw = l % 80;
            bool lval = (lh >= 2) && (lh < 58) && (lw >= 2) && (lw < 78);
            float4* orow = (float4*)(out + (size_t)bi * SDIM);
            u32* mrow = g_mask + (size_t)bi * 152;
            #pragma unroll
            for (int j = 0; j < CSLOT; j++) {
                int s4 = tid + j * CTHREADS;
                u32 nib = 0;
                if (s4 < 1200) {
                    __half2 h01, h23;
                    memcpy(&h01, &ecur[j].x, 4);
                    memcpy(&h23, &ecur[j].y, 4);
                    float2 e01 = __half22float2(h01);
                    float2 e23 = __half22float2(h23);
                    float4 c;
                    c.x = e01.x * e01.x * rowInv * colInv[j].x;
                    c.y = e01.y * e01.y * rowInv * colInv[j].y;
                    c.z = e23.x * e23.x * rowInv * colInv[j].z;
                    c.w = e23.y * e23.y * rowInv * colInv[j].w;
                    __stcs(orow + s4, c);
                    cmax[j].x = fmaxf(cmax[j].x, c.x);
                    cmax[j].y = fmaxf(cmax[j].y, c.y);
                    cmax[j].z = fmaxf(cmax[j].z, c.z);
                    cmax[j].w = fmaxf(cmax[j].w, c.w);
                    if (lval) {
                        if (c.x > 0.2f) nib |= 1u;
                        if (c.y > 0.2f) nib |= 2u;
                        if (c.z > 0.2f) nib |= 4u;
                        if (c.w > 0.2f) nib |= 8u;
                        nib &= (bnib >> (4 * j)) & 15u;
                    }
                }
                u32 v = nib << ((lane & 7) * 4);
                v |= __shfl_xor_sync(0xffffffffu, v, 1);
                v |= __shfl_xor_sync(0xffffffffu, v, 2);
                v |= __shfl_xor_sync(0xffffffffu, v, 4);
                if ((lane & 7) == 0) {
                    int w = (tid + j * CTHREADS) >> 3;
                    if (w < 150 && (tid + j * CTHREADS) < 1200) mrow[w] = v;
                }
            }
            #pragma unroll
            for (int j = 0; j < CSLOT; j++) ecur[j] = enext[j];
        }
    }
    #pragma unroll
    for (int j = 0; j < CSLOT; j++) {
        int s4 = tid + j * CTHREADS;
        if (s4 < 1200) {
            u32* cm = g_colMax + b * SDIM + s4 * 4;
            atomicMax(cm + 0, __float_as_uint(cmax[j].x));
            atomicMax(cm + 1, __float_as_uint(cmax[j].y));
            atomicMax(cm + 2, __float_as_uint(cmax[j].z));
            atomicMax(cm + 3, __float_as_uint(cmax[j].w));
        }
    }
}

// ---------------- K_match: one warp per row, scans candidate bitmask ----------------
__global__ void __launch_bounds__(256) match_kernel(float* __restrict__ out)
{
    const int wid  = threadIdx.x >> 5;
    const int lane = threadIdx.x & 31;
    const int bi   = blockIdx.x * 8 + wid;
    const int b    = bi / LDIM;

    const u32* mrow = g_mask + (size_t)bi * 152;
    u64 best = 0ull;
    for (int w = lane; w < 150; w += 32) {
        u32 m = mrow[w];
        while (m) {
            int bit = __ffs(m) - 1;
            m &= m - 1;
            int s = (w << 5) + bit;
            u64 key = ((u64)g_colMax[b * SDIM + s] << 32)
                    | (u64)(0xFFFFFFFFu - (u32)s);
            if (key > best) best = key;
        }
    }
    #pragma unroll
    for (int o = 16; o; o >>= 1) {
        u64 v = __shfl_xor_sync(0xffffffffu, best, o);
        if (v > best) best = v;
    }
    if (lane == 0) {
        float match = 0.f, sid = 0.f, mc = 0.f, kx = 0.f, ky = 0.f;
        if (best) {
            int s = (int)(0xFFFFFFFFu - (u32)(best & 0xFFFFFFFFull));
            match = 1.f;
            sid = (float)s;
            mc = out[(size_t)bi * SDIM + s];
            kx = (float)(s % 80) * 8.f;
            ky = (float)(s / 80) * 8.f;
        }
        out[OFF_MATCH + bi] = match;
        out[OFF_SID   + bi] = sid;
        out[OFF_MCONF + bi] = mc;
        out[OFF_MK1 + (size_t)bi * 2]     = kx;
        out[OFF_MK1 + (size_t)bi * 2 + 1] = ky;
    }
}

extern "C" void kernel_launch(void* const* d_in, const int* in_sizes, int n_in,
                              void* d_out, int out_size)
{
    const float* f0 = (const float*)d_in[0];
    const float* f1 = (const float*)d_in[1];
    float* out = (float*)d_out;
    const bool full = ((unsigned)out_size >= TOTAL_OUT);

    const int TOT = (BATCH * LDIM * CDIM) / 4;
    prep_kernel<<<(TOT + 255) / 256, 256>>>(f0, f1, out, full ? 1 : 0);

    dim3 gg((SDIM + 127) / 128, (LDIM + 127) / 128, BATCH);
    gemm_kernel<<<gg, 256>>>();

    invert_kernel<<<(BATCH * SDIM + 255) / 256, 256>>>();

    dim3 gc(LDIM / RPB, BATCH);
    conf_kernel<<<gc, CTHREADS>>>(out);

    if (full) match_kernel<<<(BATCH * LDIM) / 8, 256>>>(out);
}